// round 9
// baseline (speedup 1.0000x reference)
#include <cuda_runtime.h>
#include <math.h>

// ---------------- problem constants ----------------
#define LSIG   524288      // samples per batch row
#define NBATCH 32
#define NFFT   1024
#define HOP    256
#define NFRAME 2049
#define FOUT   512         // output freq bins (1..512)
#define TOUT   2048        // output frames (1..2048)

#define TCH    23          // output frames per block
#define NSLOT  24          // frame slots t0-1 .. t0+22
#define NPAIR  12          // complex-packed FFTs per block
#define NWARP  8
#define NTHR   256

// ---------------- shared memory layout (~100 KB -> 2 blocks/SM) ----------
struct Smem {
  float  win[1024];              // periodic Hann                 4 KB
  float2 spec[NSLOT][FOUT];      // (log-mag, phase) per slot    96 KB
};

// ---------------- FFT-32: in-place DIT, bit-reversed input labels --------
// Identical op DAG to the Stockham version (R2/R4-verified: same rel_err).
__device__ constexpr float FTC[16] = {
   1.0f,                    0.98078528040323044913f, 0.92387953251128675613f,
   0.83146961230254523708f, 0.70710678118654752440f, 0.55557023301960222474f,
   0.38268343236508977173f, 0.19509032201612826785f, 0.0f,
  -0.19509032201612826785f,-0.38268343236508977173f,-0.55557023301960222474f,
  -0.70710678118654752440f,-0.83146961230254523708f,-0.92387953251128675613f,
  -0.98078528040323044913f };
__device__ constexpr float FTS[16] = {
   0.0f,                    0.19509032201612826785f, 0.38268343236508977173f,
   0.55557023301960222474f, 0.70710678118654752440f, 0.83146961230254523708f,
   0.92387953251128675613f, 0.98078528040323044913f, 1.0f,
   0.98078528040323044913f, 0.92387953251128675613f, 0.83146961230254523708f,
   0.70710678118654752440f, 0.55557023301960222474f, 0.38268343236508977173f,
   0.19509032201612826785f };

__device__ constexpr int BR5[32] = {
  0,16,8,24,4,20,12,28,2,18,10,26,6,22,14,30,
  1,17,9,25,5,21,13,29,3,19,11,27,7,23,15,31 };

template <int H>
__device__ __forceinline__ void dit_stage(float2* v) {
#pragma unroll
  for (int g = 0; g < 32; g += 2 * H) {
#pragma unroll
    for (int k = 0; k < H; ++k) {
      const float c  = FTC[k * (16 / H)];
      const float sn = -FTS[k * (16 / H)];      // w = exp(-i*pi*k/H)
      float2 u = v[g + k];
      float2 t = v[g + k + H];
      float  tr = t.x * c - t.y * sn;
      float  ti = t.x * sn + t.y * c;
      v[g + k]     = make_float2(u.x + tr, u.y + ti);
      v[g + k + H] = make_float2(u.x - tr, u.y - ti);
    }
  }
}

__device__ __forceinline__ void fft32_ip(float2* v) {
  dit_stage<1>(v);
  dit_stage<2>(v);
  dit_stage<4>(v);
  dit_stage<8>(v);
  dit_stage<16>(v);
}

__device__ __forceinline__ int reflect_idx(int p) {
  p = (p < 0) ? -p : p;
  return (p >= LSIG) ? (2 * LSIG - 2 - p) : p;
}

// ---------------- main kernel ----------------
// Two consecutive frames packed into one complex 1024-pt FFT (32x32 four-step,
// one warp per packed FFT). 12 packed FFTs cover slots 0..23 of one block.
__global__ void __launch_bounds__(NTHR, 2)
stft_kernel(const float* __restrict__ x, float* __restrict__ out) {
  extern __shared__ char smraw[];
  Smem* sm = reinterpret_cast<Smem*>(smraw);

  const int tid  = threadIdx.x;
  const int lane = tid & 31;
  const int w    = tid >> 5;
  const int b    = blockIdx.y;
  const int t0   = 1 + TCH * (int)blockIdx.x;
  const int nf   = min(TCH, NFRAME - t0);   // # output frames this block

  // periodic Hann: win[n] = 0.5*(1 - cos(2*pi*n/1024))
  for (int i = tid; i < 1024; i += NTHR) {
    float sv, cv;
    sincospif((float)i * (1.0f / 512.0f), &sv, &cv);
    sm->win[i] = 0.5f - 0.5f * cv;
  }
  __syncthreads();

  const float* xb = x + (size_t)b * LSIG;

#pragma unroll 1
  for (int rep = 0; rep < 2; ++rep) {
    const int p = w + NWARP * rep;          // pair index (warp-uniform)
    if (p < NPAIR && 2 * p <= nf) {
      const int tA = t0 - 1 + 2 * p;        // frames tA (real), tA+1 (imag)
      float2 v[32];
      // load + reflect-pad + window; DIT wants bit-reversed register labels:
      // v[j] = (xwA, xwB) at sample n1 = 32*BR5[j] + lane
      const int baseA = tA * HOP - (NFFT / 2) + lane;
#pragma unroll
      for (int j = 0; j < 32; ++j) {
        const int m  = BR5[j];
        const int pa = reflect_idx(baseA + 32 * m);
        const int pb = reflect_idx(baseA + HOP + 32 * m);
        const float wn = sm->win[32 * m + lane];
        v[j] = make_float2(xb[pa] * wn, xb[pb] * wn);
      }
      // inner DFT-32 over n1 (thread = n2 = lane): natural k1 in reg index
      fft32_ip(v);
      // twiddle: W_1024^{n2*k1} via sincospif
#pragma unroll
      for (int k = 1; k < 32; ++k) {
        const int m = (lane * k) & 1023;
        float sv, cv;
        sincospif((float)m * (1.0f / 512.0f), &sv, &cv);
        float vr = v[k].x * cv + v[k].y * sv;
        float vi = -v[k].x * sv + v[k].y * cv;
        v[k] = make_float2(vr, vi);
      }
      // 32x32 warp transpose via 5-stage shfl_xor block swap (exact move):
      // after this, thread i reg j holds element (k1=i, n2=j)
#pragma unroll
      for (int mm = 1; mm < 32; mm <<= 1) {
#pragma unroll
        for (int j0 = 0; j0 < 32; ++j0) {
          if ((j0 & mm) == 0) {
            const int j1 = j0 | mm;
            const bool lo = ((lane & mm) == 0);
            float sx = lo ? v[j1].x : v[j0].x;
            float sy = lo ? v[j1].y : v[j0].y;
            float rx = __shfl_xor_sync(0xffffffffu, sx, mm);
            float ry = __shfl_xor_sync(0xffffffffu, sy, mm);
            if (lo) { v[j1].x = rx; v[j1].y = ry; }
            else    { v[j0].x = rx; v[j0].y = ry; }
          }
        }
      }
      // outer DFT-32 over n2: permute to bit-reversed labels, then DIT
      {
        float2 u[32];
#pragma unroll
        for (int j = 0; j < 32; ++j) u[j] = v[BR5[j]];
        fft32_ip(u);
#pragma unroll
        for (int j = 0; j < 32; ++j) v[j] = u[j];
      }
      // unpack packed pair + epilogue, bins 1..512 (bin = lane + 32*k2)
      const int sA = 2 * p;
#pragma unroll
      for (int k2 = 0; k2 <= 16; ++k2) {
        // conj partner F[(1024 - bin) mod 1024]:
        //   lane>0: (lane'=32-lane, reg 31-k2); lane==0: own reg (32-k2)&31
        const float2 vg = v[(31 - k2) & 31];
        const int    sl = (32 - lane) & 31;
        float gx = __shfl_sync(0xffffffffu, vg.x, sl);
        float gy = __shfl_sync(0xffffffffu, vg.y, sl);
        float2 self = v[(32 - k2) & 31];
        float  pc = (lane == 0) ? self.x : gx;
        float  pd = (lane == 0) ? self.y : gy;
        const float a = v[k2].x, bb = v[k2].y;
        // X_A = (F + conj(P))/2, X_B = (F - conj(P))/(2i)
        float xar = 0.5f * (a + pc);
        float xai = 0.5f * (bb - pd);
        float xbr = 0.5f * (bb + pd);
        float xbi = 0.5f * (pc - a);
        const int bin = lane + 32 * k2;
        if (bin >= 1 && bin <= 512) {
          float s2a = fmaxf(xar * xar + xai * xai, 1e-14f);
          float s2b = fmaxf(xbr * xbr + xbi * xbi, 1e-14f);
          float mga = (0.5f * __logf(s2a) + 17.0f) / 23.0f;
          float mgb = (0.5f * __logf(s2b) + 17.0f) / 23.0f;
          float pha = atan2f(xai, xar);
          float phb = atan2f(xbi, xbr);
          sm->spec[sA][bin - 1]     = make_float2(mga, pha);
          sm->spec[sA + 1][bin - 1] = make_float2(mgb, phb);
        }
      }
    }
  }
  __syncthreads();

  // writer: 512 freq rows / 256 threads, t-contiguous runs of nf floats
  const float PI_F  = 3.14159265358979323846f;
  const float TPI_F = 6.28318530717958647692f;
#pragma unroll
  for (int q = 0; q < 2; ++q) {
    const int ff = tid + NTHR * q;            // ff = f-1 in [0,512)
    float* mp = out + (((size_t)b * 2 + 0) * FOUT + ff) * TOUT + (t0 - 1);
    float* pp = out + (((size_t)b * 2 + 1) * FOUT + ff) * TOUT + (t0 - 1);
    float prev = sm->spec[0][ff].y;
    for (int s2 = 1; s2 <= nf; ++s2) {
      float2 cur = sm->spec[s2][ff];
      float d = cur.y - prev;
      // numpy unwrap+diff semantics: wrap dd into (-pi, pi]
      if (d > PI_F)       d -= TPI_F;
      else if (d < -PI_F) d += TPI_F;
      mp[s2 - 1] = cur.x;
      pp[s2 - 1] = d;
      prev = cur.y;
    }
  }
}

// ---------------- launch ----------------
extern "C" void kernel_launch(void* const* d_in, const int* in_sizes, int n_in,
                              void* d_out, int out_size) {
  (void)in_sizes; (void)n_in; (void)out_size;
  const float* x = (const float*)d_in[0];
  float* out = (float*)d_out;

  const int smem = (int)sizeof(Smem);
  cudaFuncSetAttribute(stft_kernel, cudaFuncAttributeMaxDynamicSharedMemorySize, smem);

  dim3 grid((TOUT + TCH - 1) / TCH, NBATCH);   // 90 x 32
  stft_kernel<<<grid, NTHR, smem>>>(x, out);
}

// round 12
// speedup vs baseline: 1.0426x; 1.0426x over previous
#include <cuda_runtime.h>
#include <math.h>

// ---------------- problem constants ----------------
#define LSIG   524288      // samples per batch row
#define NBATCH 32
#define NFFT   1024
#define HOP    256
#define NFRAME 2049
#define FOUT   512         // output freq bins (1..512)
#define TOUT   2048        // output frames (1..2048)

#define TCH    31          // output frames per block
#define NSLOT  32          // frame slots t0-1 .. t0+30
#define NPAIR  16          // complex-packed FFTs per block
#define NWARP  8
#define NTHR   256

// ---------------- shared memory layout (~211 KB -> 1 block/SM) ----------
struct Smem {
  float  win[1024];              // periodic Hann                     4 KB
  float  ctab[1024];             // cos(2*pi*m/1024)                  4 KB
  float  stab[1024];             // sin(2*pi*m/1024)                  4 KB
  float2 trbuf[NWARP][32 * 33];  // per-warp 32x32 float2 transpose  67.6 KB
  float2 spec[NSLOT][FOUT];      // (log-mag, phase) per frame slot  131 KB
};

// ---------------- FFT-32 (register Stockham, natural in/out) ------------
__device__ constexpr float FTC[16] = {
   1.0f,                    0.98078528040323044913f, 0.92387953251128675613f,
   0.83146961230254523708f, 0.70710678118654752440f, 0.55557023301960222474f,
   0.38268343236508977173f, 0.19509032201612826785f, 0.0f,
  -0.19509032201612826785f,-0.38268343236508977173f,-0.55557023301960222474f,
  -0.70710678118654752440f,-0.83146961230254523708f,-0.92387953251128675613f,
  -0.98078528040323044913f };
__device__ constexpr float FTS[16] = {
   0.0f,                    0.19509032201612826785f, 0.38268343236508977173f,
   0.55557023301960222474f, 0.70710678118654752440f, 0.83146961230254523708f,
   0.92387953251128675613f, 0.98078528040323044913f, 1.0f,
   0.98078528040323044913f, 0.92387953251128675613f, 0.83146961230254523708f,
   0.70710678118654752440f, 0.55557023301960222474f, 0.38268343236508977173f,
   0.19509032201612826785f };

template <int NS>
__device__ __forceinline__ void fft32_stage(const float2* s, float2* d) {
#pragma unroll
  for (int j = 0; j < 16; ++j) {
    const int   k  = j & (NS - 1);
    const float c  = FTC[k * (16 / NS)];
    const float sn = -FTS[k * (16 / NS)];   // w = exp(-i*pi*k/NS)
    float2 u = s[j];
    float2 t = s[j + 16];
    float  tr = t.x * c - t.y * sn;
    float  ti = t.x * sn + t.y * c;
    const int o = (j / NS) * (2 * NS) + k;
    d[o]      = make_float2(u.x + tr, u.y + ti);
    d[o + NS] = make_float2(u.x - tr, u.y - ti);
  }
}

__device__ __forceinline__ void fft32(float2* v) {
  float2 t[32];
  fft32_stage<1>(v, t);
  fft32_stage<2>(t, v);
  fft32_stage<4>(v, t);
  fft32_stage<8>(t, v);
  fft32_stage<16>(v, t);
#pragma unroll
  for (int i = 0; i < 32; ++i) v[i] = t[i];
}

__device__ __forceinline__ int reflect_idx(int p) {
  p = (p < 0) ? -p : p;
  return (p >= LSIG) ? (2 * LSIG - 2 - p) : p;
}

// ---------------- main kernel ----------------
// Two consecutive frames packed into one complex 1024-pt FFT (32x32 four-step,
// one warp per packed FFT). 16 packed FFTs cover slots 0..31 of one block.
__global__ void __launch_bounds__(NTHR, 1)
stft_kernel(const float* __restrict__ x, float* __restrict__ out) {
  extern __shared__ char smraw[];
  Smem* sm = reinterpret_cast<Smem*>(smraw);

  const int tid  = threadIdx.x;
  const int lane = tid & 31;
  const int w    = tid >> 5;
  const int b    = blockIdx.y;
  const int t0   = 1 + TCH * (int)blockIdx.x;
  const int nf   = min(TCH, NFRAME - t0);   // # output frames this block

  // tables (bit-identical to sincospif-on-the-fly)
  for (int i = tid; i < 1024; i += NTHR) {
    float sv, cv;
    sincospif((float)i * (1.0f / 512.0f), &sv, &cv);
    sm->win[i]  = 0.5f - 0.5f * cv;
    sm->ctab[i] = cv;
    sm->stab[i] = sv;
  }
  __syncthreads();

  const float* xb = x + (size_t)b * LSIG;
  float2* tb = sm->trbuf[w];

#pragma unroll 1
  for (int rep = 0; rep < NPAIR / NWARP; ++rep) {
    const int p = w + NWARP * rep;          // pair index (warp-uniform)
    if (2 * p <= nf) {
      const int tA = t0 - 1 + 2 * p;        // frames tA (real), tA+1 (imag)
      float2 v[32];
      // load + window: v[j] = (xwA, xwB) at sample 32*j+lane
      const int baseA = tA * HOP - (NFFT / 2) + lane;
      const bool interior = (tA >= 2) && (tA <= 2043);  // no reflect needed
      if (interior) {
#pragma unroll
        for (int j = 0; j < 32; ++j) {
          const int pa = baseA + 32 * j;
          const float wn = sm->win[32 * j + lane];
          v[j] = make_float2(xb[pa] * wn, xb[pa + HOP] * wn);
        }
      } else {
#pragma unroll
        for (int j = 0; j < 32; ++j) {
          const int pa = reflect_idx(baseA + 32 * j);
          const int pb = reflect_idx(baseA + HOP + 32 * j);
          const float wn = sm->win[32 * j + lane];
          v[j] = make_float2(xb[pa] * wn, xb[pb] * wn);
        }
      }
      // inner DFT-32 over n1 (thread = n2 = lane)
      fft32(v);
      // twiddle: W_1024^{n2*k1} from split smem tables
#pragma unroll
      for (int k = 1; k < 32; ++k) {
        const int m = (lane * k) & 1023;
        const float cv = sm->ctab[m];
        const float sv = sm->stab[m];
        float vr = v[k].x * cv + v[k].y * sv;
        float vi = -v[k].x * sv + v[k].y * cv;
        v[k] = make_float2(vr, vi);
      }
      // 32x32 float2 transpose (pad 33)
      __syncwarp();
#pragma unroll
      for (int k = 0; k < 32; ++k) tb[lane * 33 + k] = v[k];
      __syncwarp();
#pragma unroll
      for (int k = 0; k < 32; ++k) v[k] = tb[k * 33 + lane];
      // outer DFT-32 over n2 -> F[lane + 32*k2]
      fft32(v);
      // unpack packed pair + epilogue, bins 1..512
      const int sA = 2 * p;
#pragma unroll
      for (int k2 = 0; k2 <= 16; ++k2) {
        // conj partner F[(1024 - bin) mod 1024]:
        //   lane>0: (lane'=32-lane, reg 31-k2); lane==0: own reg (32-k2)&31
        const float2 vg = v[(31 - k2) & 31];
        const int    sl = (32 - lane) & 31;
        float gx = __shfl_sync(0xffffffffu, vg.x, sl);
        float gy = __shfl_sync(0xffffffffu, vg.y, sl);
        float2 self = v[(32 - k2) & 31];
        float  pc = (lane == 0) ? self.x : gx;
        float  pd = (lane == 0) ? self.y : gy;
        const float a = v[k2].x, bb = v[k2].y;
        // X_A = (F + conj(P))/2, X_B = (F - conj(P))/(2i)
        float xar = 0.5f * (a + pc);
        float xai = 0.5f * (bb - pd);
        float xbr = 0.5f * (bb + pd);
        float xbi = 0.5f * (pc - a);
        const int bin = lane + 32 * k2;
        if (bin >= 1 && bin <= 512) {
          float s2a = fmaxf(xar * xar + xai * xai, 1e-14f);
          float s2b = fmaxf(xbr * xbr + xbi * xbi, 1e-14f);
          float mga = (0.5f * __logf(s2a) + 17.0f) / 23.0f;
          float mgb = (0.5f * __logf(s2b) + 17.0f) / 23.0f;
          float pha = atan2f(xai, xar);
          float phb = atan2f(xbi, xbr);
          sm->spec[sA][bin - 1]     = make_float2(mga, pha);
          sm->spec[sA + 1][bin - 1] = make_float2(mgb, phb);
        }
      }
    }
  }
  __syncthreads();

  // writer: 512 freq rows / 256 threads, t-contiguous runs of nf floats
  const float PI_F  = 3.14159265358979323846f;
  const float TPI_F = 6.28318530717958647692f;
#pragma unroll
  for (int q = 0; q < 2; ++q) {
    const int ff = tid + NTHR * q;            // ff = f-1 in [0,512)
    float* mp = out + (((size_t)b * 2 + 0) * FOUT + ff) * TOUT + (t0 - 1);
    float* pp = out + (((size_t)b * 2 + 1) * FOUT + ff) * TOUT + (t0 - 1);
    float prev = sm->spec[0][ff].y;
    for (int s2 = 1; s2 <= nf; ++s2) {
      float2 cur = sm->spec[s2][ff];
      float d = cur.y - prev;
      // numpy unwrap+diff semantics: wrap dd into (-pi, pi]
      if (d > PI_F)       d -= TPI_F;
      else if (d < -PI_F) d += TPI_F;
      mp[s2 - 1] = cur.x;
      pp[s2 - 1] = d;
      prev = cur.y;
    }
  }
}

// ---------------- launch ----------------
extern "C" void kernel_launch(void* const* d_in, const int* in_sizes, int n_in,
                              void* d_out, int out_size) {
  (void)in_sizes; (void)n_in; (void)out_size;
  const float* x = (const float*)d_in[0];
  float* out = (float*)d_out;

  const int smem = (int)sizeof(Smem);
  cudaFuncSetAttribute(stft_kernel, cudaFuncAttributeMaxDynamicSharedMemorySize, smem);

  dim3 grid((TOUT + TCH - 1) / TCH, NBATCH);   // 67 x 32
  stft_kernel<<<grid, NTHR, smem>>>(x, out);
}

// round 13
// speedup vs baseline: 1.4938x; 1.4328x over previous
#include <cuda_runtime.h>
#include <math.h>

// ---------------- problem constants ----------------
#define LSIG   524288      // samples per batch row
#define NBATCH 32
#define NFFT   1024
#define HOP    256
#define NFRAME 2049
#define FOUT   512         // output freq bins (1..512)
#define TOUT   2048        // output frames (1..2048)

#define TCH    31          // output frames per block
#define NSLOT  32          // frame slots t0-1 .. t0+30
#define NPAIR  16          // complex-packed FFTs per block
#define NWARP  8
#define NTHR   256

// ---------------- shared memory layout (~211 KB -> 1 block/SM) ----------
// smag/sph use 513-float rows: odd word stride => writer's lane-strided LDS
// (stride 513 words) hits consecutive banks -> conflict-free.
struct Smem {
  float  win[1024];              // periodic Hann                     4 KB
  float  ctab[1024];             // cos(2*pi*m/1024)                  4 KB
  float  stab[1024];             // sin(2*pi*m/1024)                  4 KB
  float2 trbuf[NWARP][32 * 33];  // per-warp 32x32 float2 transpose  67.6 KB
  float  smag[NSLOT][FOUT + 1];  // normalized log-mag per slot      65.7 KB
  float  sph [NSLOT][FOUT + 1];  // phase per slot                   65.7 KB
};

// ---------------- FFT-32 (register Stockham, natural in/out) ------------
__device__ constexpr float FTC[16] = {
   1.0f,                    0.98078528040323044913f, 0.92387953251128675613f,
   0.83146961230254523708f, 0.70710678118654752440f, 0.55557023301960222474f,
   0.38268343236508977173f, 0.19509032201612826785f, 0.0f,
  -0.19509032201612826785f,-0.38268343236508977173f,-0.55557023301960222474f,
  -0.70710678118654752440f,-0.83146961230254523708f,-0.92387953251128675613f,
  -0.98078528040323044913f };
__device__ constexpr float FTS[16] = {
   0.0f,                    0.19509032201612826785f, 0.38268343236508977173f,
   0.55557023301960222474f, 0.70710678118654752440f, 0.83146961230254523708f,
   0.92387953251128675613f, 0.98078528040323044913f, 1.0f,
   0.98078528040323044913f, 0.92387953251128675613f, 0.83146961230254523708f,
   0.70710678118654752440f, 0.55557023301960222474f, 0.38268343236508977173f,
   0.19509032201612826785f };

template <int NS>
__device__ __forceinline__ void fft32_stage(const float2* s, float2* d) {
#pragma unroll
  for (int j = 0; j < 16; ++j) {
    const int   k  = j & (NS - 1);
    const float c  = FTC[k * (16 / NS)];
    const float sn = -FTS[k * (16 / NS)];   // w = exp(-i*pi*k/NS)
    float2 u = s[j];
    float2 t = s[j + 16];
    float  tr = t.x * c - t.y * sn;
    float  ti = t.x * sn + t.y * c;
    const int o = (j / NS) * (2 * NS) + k;
    d[o]      = make_float2(u.x + tr, u.y + ti);
    d[o + NS] = make_float2(u.x - tr, u.y - ti);
  }
}

__device__ __forceinline__ void fft32(float2* v) {
  float2 t[32];
  fft32_stage<1>(v, t);
  fft32_stage<2>(t, v);
  fft32_stage<4>(v, t);
  fft32_stage<8>(t, v);
  fft32_stage<16>(v, t);
#pragma unroll
  for (int i = 0; i < 32; ++i) v[i] = t[i];
}

__device__ __forceinline__ int reflect_idx(int p) {
  p = (p < 0) ? -p : p;
  return (p >= LSIG) ? (2 * LSIG - 2 - p) : p;
}

// ---------------- main kernel ----------------
// Two consecutive frames packed into one complex 1024-pt FFT (32x32 four-step,
// one warp per packed FFT). 16 packed FFTs cover slots 0..31 of one block.
__global__ void __launch_bounds__(NTHR, 1)
stft_kernel(const float* __restrict__ x, float* __restrict__ out) {
  extern __shared__ char smraw[];
  Smem* sm = reinterpret_cast<Smem*>(smraw);

  const int tid  = threadIdx.x;
  const int lane = tid & 31;
  const int w    = tid >> 5;
  const int b    = blockIdx.y;
  const int t0   = 1 + TCH * (int)blockIdx.x;
  const int nf   = min(TCH, NFRAME - t0);   // # output frames this block

  // tables (bit-identical to sincospif-on-the-fly)
  for (int i = tid; i < 1024; i += NTHR) {
    float sv, cv;
    sincospif((float)i * (1.0f / 512.0f), &sv, &cv);
    sm->win[i]  = 0.5f - 0.5f * cv;
    sm->ctab[i] = cv;
    sm->stab[i] = sv;
  }
  __syncthreads();

  const float* xb = x + (size_t)b * LSIG;
  float2* tb = sm->trbuf[w];

#pragma unroll 1
  for (int rep = 0; rep < NPAIR / NWARP; ++rep) {
    const int p = w + NWARP * rep;          // pair index (warp-uniform)
    if (2 * p <= nf) {
      const int tA = t0 - 1 + 2 * p;        // frames tA (real), tA+1 (imag)
      float2 v[32];
      // load + window: v[j] = (xwA, xwB) at sample 32*j+lane
      const int baseA = tA * HOP - (NFFT / 2) + lane;
      const bool interior = (tA >= 2) && (tA <= 2043);  // no reflect needed
      if (interior) {
#pragma unroll
        for (int j = 0; j < 32; ++j) {
          const int pa = baseA + 32 * j;
          const float wn = sm->win[32 * j + lane];
          v[j] = make_float2(xb[pa] * wn, xb[pa + HOP] * wn);
        }
      } else {
#pragma unroll
        for (int j = 0; j < 32; ++j) {
          const int pa = reflect_idx(baseA + 32 * j);
          const int pb = reflect_idx(baseA + HOP + 32 * j);
          const float wn = sm->win[32 * j + lane];
          v[j] = make_float2(xb[pa] * wn, xb[pb] * wn);
        }
      }
      // inner DFT-32 over n1 (thread = n2 = lane)
      fft32(v);
      // twiddle: W_1024^{n2*k1} from split smem tables
#pragma unroll
      for (int k = 1; k < 32; ++k) {
        const int m = (lane * k) & 1023;
        const float cv = sm->ctab[m];
        const float sv = sm->stab[m];
        float vr = v[k].x * cv + v[k].y * sv;
        float vi = -v[k].x * sv + v[k].y * cv;
        v[k] = make_float2(vr, vi);
      }
      // 32x32 float2 transpose (pad 33)
      __syncwarp();
#pragma unroll
      for (int k = 0; k < 32; ++k) tb[lane * 33 + k] = v[k];
      __syncwarp();
#pragma unroll
      for (int k = 0; k < 32; ++k) v[k] = tb[k * 33 + lane];
      // outer DFT-32 over n2 -> F[lane + 32*k2]
      fft32(v);
      // unpack packed pair + epilogue, bins 1..512
      const int sA = 2 * p;
#pragma unroll
      for (int k2 = 0; k2 <= 16; ++k2) {
        // conj partner F[(1024 - bin) mod 1024]:
        //   lane>0: (lane'=32-lane, reg 31-k2); lane==0: own reg (32-k2)&31
        const float2 vg = v[(31 - k2) & 31];
        const int    sl = (32 - lane) & 31;
        float gx = __shfl_sync(0xffffffffu, vg.x, sl);
        float gy = __shfl_sync(0xffffffffu, vg.y, sl);
        float2 self = v[(32 - k2) & 31];
        float  pc = (lane == 0) ? self.x : gx;
        float  pd = (lane == 0) ? self.y : gy;
        const float a = v[k2].x, bb = v[k2].y;
        // X_A = (F + conj(P))/2, X_B = (F - conj(P))/(2i)
        float xar = 0.5f * (a + pc);
        float xai = 0.5f * (bb - pd);
        float xbr = 0.5f * (bb + pd);
        float xbi = 0.5f * (pc - a);
        const int bin = lane + 32 * k2;
        if (bin >= 1 && bin <= 512) {
          float s2a = fmaxf(xar * xar + xai * xai, 1e-14f);
          float s2b = fmaxf(xbr * xbr + xbi * xbi, 1e-14f);
          float mga = (0.5f * __logf(s2a) + 17.0f) / 23.0f;
          float mgb = (0.5f * __logf(s2b) + 17.0f) / 23.0f;
          float pha = atan2f(xai, xar);
          float phb = atan2f(xbi, xbr);
          sm->smag[sA][bin - 1]     = mga;
          sm->sph [sA][bin - 1]     = pha;
          sm->smag[sA + 1][bin - 1] = mgb;
          sm->sph [sA + 1][bin - 1] = phb;
        }
      }
    }
  }
  __syncthreads();

  // writer: lanes run along time. Warp w owns rows r = w*128 + i,
  // r = ch*512 + ff (ch warp-uniform). Each STG = nf consecutive floats
  // (<=124 B = 4 sectors) instead of 32 scattered 8KB-strided words.
  const float PI_F  = 3.14159265358979323846f;
  const float TPI_F = 6.28318530717958647692f;
  const int s = lane;                        // time slot offset, s < nf active
#pragma unroll 1
  for (int i = 0; i < 128; ++i) {
    const int r  = w * 128 + i;              // 0..1023
    const int ch = r >> 9;                   // warp-uniform
    const int ff = r & 511;
    if (s < nf) {
      float val;
      if (ch == 0) {
        val = sm->smag[s + 1][ff];
      } else {
        float d = sm->sph[s + 1][ff] - sm->sph[s][ff];
        // numpy unwrap+diff semantics: wrap dd into (-pi, pi]
        if (d > PI_F)       d -= TPI_F;
        else if (d < -PI_F) d += TPI_F;
        val = d;
      }
      out[(((size_t)b * 2 + ch) * FOUT + ff) * TOUT + (t0 - 1) + s] = val;
    }
  }
}

// ---------------- launch ----------------
extern "C" void kernel_launch(void* const* d_in, const int* in_sizes, int n_in,
                              void* d_out, int out_size) {
  (void)in_sizes; (void)n_in; (void)out_size;
  const float* x = (const float*)d_in[0];
  float* out = (float*)d_out;

  const int smem = (int)sizeof(Smem);
  cudaFuncSetAttribute(stft_kernel, cudaFuncAttributeMaxDynamicSharedMemorySize, smem);

  dim3 grid((TOUT + TCH - 1) / TCH, NBATCH);   // 67 x 32
  stft_kernel<<<grid, NTHR, smem>>>(x, out);
}